// round 4
// baseline (speedup 1.0000x reference)
#include <cuda_runtime.h>
#include <math.h>

#define VOCAB 32000
#define DIM   1024
#define NBITS 15
#define NTOK  4096        // 4 * 1024 tokens
#define KDIM  1024

// Output layout (floats), reference tuple order:
//   id_emb  [NTOK, DIM]      @ 0
//   bit_emb [NTOK, DIM]      @ 4194304
//   logit   [NTOK, VOCAB]    @ 8388608
//   logit_w [NTOK, NBITS]    @ 8388608 + 131072000
#define OFF_BIT   4194304u
#define OFF_LOGIT 8388608u
#define OFF_LW    (8388608u + 131072000u)

// ---------------------------------------------------------------------------
// 1) id_emb: gather weight rows. Vectorized float4. 1M float4 total.
// ---------------------------------------------------------------------------
__global__ void id_embed_kernel(const int* __restrict__ ids,
                                const float* __restrict__ weight,
                                float* __restrict__ out)
{
    int idx = blockIdx.x * blockDim.x + threadIdx.x;   // 0 .. 1048575 (float4 units)
    int token = idx >> 8;            // DIM/4 = 256 float4 per token
    int d4    = idx & 255;
    int id    = ids[token];
    id = min(max(id, 0), VOCAB - 1);   // defensive clamp (matches jax gather clip)
    const float4* src = reinterpret_cast<const float4*>(weight + (size_t)id * DIM);
    reinterpret_cast<float4*>(out)[idx] = src[d4];
}

// ---------------------------------------------------------------------------
// 2) bit_emb: sum_j sign_j(id) * weight_bit[j]. MSB-first bits.
// ---------------------------------------------------------------------------
__global__ void bit_embed_kernel(const int* __restrict__ ids,
                                 const float* __restrict__ wbit,
                                 float* __restrict__ out)
{
    int idx = blockIdx.x * blockDim.x + threadIdx.x;   // float4 units
    int token = idx >> 8;
    int d4    = idx & 255;
    int id    = ids[token];
    id = min(max(id, 0), VOCAB - 1);
    const float4* wb = reinterpret_cast<const float4*>(wbit);
    float4 acc = make_float4(0.f, 0.f, 0.f, 0.f);
#pragma unroll
    for (int j = 0; j < NBITS; j++) {
        float4 w = wb[j * 256 + d4];
        float s = ((id >> (14 - j)) & 1) ? 1.0f : -1.0f;
        acc.x += s * w.x; acc.y += s * w.y; acc.z += s * w.z; acc.w += s * w.w;
    }
    reinterpret_cast<float4*>(out)[idx] = acc;
}

// ---------------------------------------------------------------------------
// 3) logit = tensor[4096,1024] @ weight[32000,1024]^T  (NT SGEMM, fp32 exact)
//    128x128 tile, BK=8, 256 threads, 8x8 microkernel, double-buffered SMEM.
//    M=4096 (32 tiles), N=32000 (250 tiles), K=1024 (128 k-steps). No edges.
// ---------------------------------------------------------------------------
__global__ __launch_bounds__(256)
void sgemm_nt_kernel(const float* __restrict__ A,   // [4096, 1024]
                     const float* __restrict__ B,   // [32000, 1024]
                     float* __restrict__ C)         // [4096, 32000]
{
    __shared__ float As[2][8][128];
    __shared__ float Bs[2][8][128];

    const int tid = threadIdx.x;
    const int tx  = tid & 15;        // 0..15 -> 8 N-cols each
    const int ty  = tid >> 4;        // 0..15 -> 8 M-rows each
    const int mBase = blockIdx.y * 128;
    const int nBase = blockIdx.x * 128;

    // Global-load assignment: thread t loads float4 #t of the 128x8 tile
    const int lrow = tid >> 1;        // 0..127
    const int lcol = (tid & 1) * 4;   // 0 or 4
    const float* Aptr = A + (size_t)(mBase + lrow) * KDIM + lcol;
    const float* Bptr = B + (size_t)(nBase + lrow) * KDIM + lcol;

    float acc[8][8];
#pragma unroll
    for (int i = 0; i < 8; i++)
#pragma unroll
        for (int j = 0; j < 8; j++) acc[i][j] = 0.f;

    // prologue: load k-tile 0 into stage 0
    {
        float4 av = *reinterpret_cast<const float4*>(Aptr);
        float4 bv = *reinterpret_cast<const float4*>(Bptr);
        As[0][lcol + 0][lrow] = av.x; As[0][lcol + 1][lrow] = av.y;
        As[0][lcol + 2][lrow] = av.z; As[0][lcol + 3][lrow] = av.w;
        Bs[0][lcol + 0][lrow] = bv.x; Bs[0][lcol + 1][lrow] = bv.y;
        Bs[0][lcol + 2][lrow] = bv.z; Bs[0][lcol + 3][lrow] = bv.w;
    }
    __syncthreads();

    const int NSTEP = KDIM / 8;       // 128
    for (int kt = 0; kt < NSTEP; kt++) {
        const int buf = kt & 1;
        float4 av, bv;
        if (kt + 1 < NSTEP) {
            av = *reinterpret_cast<const float4*>(Aptr + (kt + 1) * 8);
            bv = *reinterpret_cast<const float4*>(Bptr + (kt + 1) * 8);
        }

#pragma unroll
        for (int kk = 0; kk < 8; kk++) {
            float a[8], b[8];
            *reinterpret_cast<float4*>(a)     = *reinterpret_cast<const float4*>(&As[buf][kk][ty * 8]);
            *reinterpret_cast<float4*>(a + 4) = *reinterpret_cast<const float4*>(&As[buf][kk][ty * 8 + 4]);
            *reinterpret_cast<float4*>(b)     = *reinterpret_cast<const float4*>(&Bs[buf][kk][tx * 8]);
            *reinterpret_cast<float4*>(b + 4) = *reinterpret_cast<const float4*>(&Bs[buf][kk][tx * 8 + 4]);
#pragma unroll
            for (int i = 0; i < 8; i++)
#pragma unroll
                for (int j = 0; j < 8; j++)
                    acc[i][j] += a[i] * b[j];
        }

        if (kt + 1 < NSTEP) {
            const int nb = buf ^ 1;
            As[nb][lcol + 0][lrow] = av.x; As[nb][lcol + 1][lrow] = av.y;
            As[nb][lcol + 2][lrow] = av.z; As[nb][lcol + 3][lrow] = av.w;
            Bs[nb][lcol + 0][lrow] = bv.x; Bs[nb][lcol + 1][lrow] = bv.y;
            Bs[nb][lcol + 2][lrow] = bv.z; Bs[nb][lcol + 3][lrow] = bv.w;
            __syncthreads();
        }
    }

#pragma unroll
    for (int i = 0; i < 8; i++) {
        float* crow = C + (size_t)(mBase + ty * 8 + i) * VOCAB + nBase + tx * 8;
        *reinterpret_cast<float4*>(crow)     = *reinterpret_cast<float4*>(&acc[i][0]);
        *reinterpret_cast<float4*>(crow + 4) = *reinterpret_cast<float4*>(&acc[i][4]);
    }
}

// ---------------------------------------------------------------------------
// 4) logit_w: per-row softmax over 32000 + projection onto +-1 bit codes.
//    logit_w[row, j] = 2 * P(bit_{14-j} = 1) - 1, bits MSB-first.
//    One block (256 thr) per row. With stride-256 iteration the low 8 bits
//    of the vocab index equal tid, so only 7 conditional accumulators are
//    needed per element; low-8 bitsums derive from the thread's own total.
// ---------------------------------------------------------------------------
__global__ __launch_bounds__(256)
void softmax_bits_kernel(const float* __restrict__ logit,
                         float* __restrict__ out_lw)
{
    const int row = blockIdx.x;
    const int tid = threadIdx.x;
    const float* L = logit + (size_t)row * VOCAB;

    // pass 1: row max
    float m = -1e30f;
    for (int i = tid; i < VOCAB; i += 256) m = fmaxf(m, L[i]);
#pragma unroll
    for (int o = 16; o; o >>= 1) m = fmaxf(m, __shfl_xor_sync(0xffffffffu, m, o));
    __shared__ float wmax[8];
    if ((tid & 31) == 0) wmax[tid >> 5] = m;
    __syncthreads();
    m = wmax[0];
#pragma unroll
    for (int w = 1; w < 8; w++) m = fmaxf(m, wmax[w]);

    // pass 2: exp-sum + high-bit sums. i = tid + 256*t, t in [0,125)
    float s = 0.f;
    float bh[7] = {0.f, 0.f, 0.f, 0.f, 0.f, 0.f, 0.f};
    for (int t = 0; t < VOCAB / 256; t++) {
        float e = __expf(L[tid + (t << 8)] - m);
        s += e;
#pragma unroll
        for (int k = 0; k < 7; k++)
            bh[k] += ((t >> k) & 1) ? e : 0.f;
    }

    // assemble 16 partials: bs[0..14] bitsums (bit k of vocab idx), bs[15]=total
    float bs[16];
#pragma unroll
    for (int k = 0; k < 8; k++) bs[k] = ((tid >> k) & 1) ? s : 0.f;
#pragma unroll
    for (int k = 0; k < 7; k++) bs[k + 8] = bh[k];
    bs[15] = s;

    // reduce 16 values across warp, then across 8 warps
#pragma unroll
    for (int q = 0; q < 16; q++) {
#pragma unroll
        for (int o = 16; o; o >>= 1)
            bs[q] += __shfl_xor_sync(0xffffffffu, bs[q], o);
    }
    __shared__ float red[8][16];
    if ((tid & 31) == 0) {
#pragma unroll
        for (int q = 0; q < 16; q++) red[tid >> 5][q] = bs[q];
    }
    __syncthreads();
    if (tid == 0) {
        float tot[16];
#pragma unroll
        for (int q = 0; q < 16; q++) {
            float v = 0.f;
#pragma unroll
            for (int w = 0; w < 8; w++) v += red[w][q];
            tot[q] = v;
        }
        float inv = 1.0f / tot[15];
#pragma unroll
        for (int k = 0; k < 15; k++) {
            // shift k corresponds to output position j = 14 - k (MSB first)
            out_lw[(size_t)row * NBITS + (14 - k)] = 2.0f * tot[k] * inv - 1.0f;
        }
    }
}

// ---------------------------------------------------------------------------
extern "C" void kernel_launch(void* const* d_in, const int* in_sizes, int n_in,
                              void* d_out, int out_size)
{
    const int*   ids    = (const int*)  d_in[0];   // [4,1024] int32
    const float* tensor = (const float*)d_in[1];   // [4,1024,1024]
    const float* weight = (const float*)d_in[2];   // [32000,1024]
    const float* wbit   = (const float*)d_in[3];   // [15,1024]

    float* out     = (float*)d_out;
    float* id_emb  = out;
    float* bit_emb = out + OFF_BIT;
    float* logit   = out + OFF_LOGIT;
    float* lw      = out + OFF_LW;

    // 1M float4 each for the two embedding outputs
    id_embed_kernel <<<4096, 256>>>(ids, weight, id_emb);
    bit_embed_kernel<<<4096, 256>>>(ids, wbit, bit_emb);

    dim3 grid(VOCAB / 128, NTOK / 128);   // 250 x 32
    sgemm_nt_kernel<<<grid, 256>>>(tensor, weight, logit);

    softmax_bits_kernel<<<NTOK, 256>>>(logit, lw);
}